// round 8
// baseline (speedup 1.0000x reference)
#include <cuda_runtime.h>
#include <cuda_bf16.h>

// MomentumLSTM v7: diagonal f32x2 — natural weight pairs (w_u0,w_u1) x natural
// batch pairs (h_b0,h_b1) via accA += w*h and accB += w*swap(h). Kills the
// 16-MOV/k weight-duplication tax of v6. i/f/o gate rows pre-scaled by 0.5 so
// sigmoid = fmaf(0.5, tanh(acc), 0.5). Persistent 152x384, warp-local recurrence.

#define BATCH  32768
#define TT     60
#define DD     7
#define H1     64
#define G1     256
#define H2     32
#define G2     128
#define NT     384
#define GRID   152
#define TB     8                 // batches per warp-task
#define NTASKS (BATCH / TB)      // 4096
#define WSLOTS (GRID * 12)       // 1824
#define HS1    10                // even stride: [64][10] per-warp h1 slab
#define HS2    10                // [32][10]
#define XS     8                 // [7][8]

// SMEM float offsets
#define OFF_W1T 0                // [71][256] rows 0..6 x-w, 7..70 h-w (i/f/o rows pre-scaled 0.5)
#define OFF_W2T 18176            // [96][128]
#define OFF_B1  30464            // [256]
#define OFF_B2  30720            // [128]
#define OFF_H1  30848            // 12 x 640
#define OFF_H2  38528            // 12 x 320
#define OFF_X   42368            // 12 x 64
#define SMEM_FLOATS 43136
#define SMEM_BYTES  (SMEM_FLOATS * 4)   // 172544

typedef unsigned long long u64t;

__device__ __forceinline__ u64t pk2(float a, float b) {
    u64t r; asm("mov.b64 %0, {%1, %2};" : "=l"(r) : "f"(a), "f"(b)); return r;
}
__device__ __forceinline__ void upk(u64t v, float& lo, float& hi) {
    asm("mov.b64 {%0, %1}, %2;" : "=f"(lo), "=f"(hi) : "l"(v));
}
__device__ __forceinline__ u64t swp(u64t v) {      // (lo,hi) -> (hi,lo): 2 MOV32
    float lo, hi; upk(v, lo, hi); return pk2(hi, lo);
}
__device__ __forceinline__ u64t fma2(u64t a, u64t b, u64t c) {
    u64t d; asm("fma.rn.f32x2 %0, %1, %2, %3;" : "=l"(d) : "l"(a), "l"(b), "l"(c)); return d;
}
__device__ __forceinline__ u64t lds64(const float* p) {
    return *reinterpret_cast<const u64t*>(p);
}
__device__ __forceinline__ void sts64(float* p, u64t v) {
    *reinterpret_cast<u64t*>(p) = v;
}
__device__ __forceinline__ float tanha(float x) {
    float y; asm("tanh.approx.f32 %0, %1;" : "=f"(y) : "f"(x)); return y;
}
// acc already holds x/2 (weights pre-scaled): sigmoid(x) = 0.5*tanh(x/2)+0.5
__device__ __forceinline__ float sig_h(float halfx) {
    return fmaf(0.5f, tanha(halfx), 0.5f);
}
__device__ __forceinline__ float sigx(float x) {   // exact, output only
    return __fdividef(1.0f, 1.0f + __expf(-x));
}

__global__ void __launch_bounds__(NT, 1)
momentum_lstm_kernel(const float* __restrict__ x,
                     const float* __restrict__ Wih1, const float* __restrict__ Whh1,
                     const float* __restrict__ bih1, const float* __restrict__ bhh1,
                     const float* __restrict__ Wih2, const float* __restrict__ Whh2,
                     const float* __restrict__ bih2, const float* __restrict__ bhh2,
                     const float* __restrict__ Wd,  const float* __restrict__ bd,
                     const float* __restrict__ Wo,  const float* __restrict__ bo,
                     float* __restrict__ out)
{
    extern __shared__ float sm[];
    float* sW1T = sm + OFF_W1T;
    float* sW2T = sm + OFF_W2T;
    float* sB1  = sm + OFF_B1;
    float* sB2  = sm + OFF_B2;

    const int tid  = threadIdx.x;
    const int lane = tid & 31;
    const int wid  = tid >> 5;

    float* sH1w = sm + OFF_H1 + wid * (H1 * HS1);
    float* sH2w = sm + OFF_H2 + wid * (H2 * HS2);
    float* sXw  = sm + OFF_X  + wid * 64;

    // ---------------- staging: transpose + pre-scale i/f/o rows by 0.5 ----------------
    for (int i = tid; i < DD * G1; i += NT) {
        int d = i >> 8, g = i & 255;
        float s = ((g >> 6) == 2) ? 1.0f : 0.5f;       // gate order i,f,g,o
        sW1T[d * G1 + g] = s * Wih1[g * DD + d];
    }
    for (int i = tid; i < H1 * G1; i += NT) {
        int k = i >> 8, g = i & 255;
        float s = ((g >> 6) == 2) ? 1.0f : 0.5f;
        sW1T[(DD + k) * G1 + g] = s * Whh1[g * H1 + k];
    }
    for (int i = tid; i < (H1 + H2) * G2; i += NT) {
        int k = i >> 7, g = i & 127;
        float s = ((g >> 5) == 2) ? 1.0f : 0.5f;
        sW2T[i] = s * ((k < H1) ? Wih2[g * H1 + k] : Whh2[g * H2 + (k - H1)]);
    }
    if (tid < G1) {
        float s = ((tid >> 6) == 2) ? 1.0f : 0.5f;
        sB1[tid] = s * (bih1[tid] + bhh1[tid]);
    }
    if (tid < G2) {
        float s = ((tid >> 5) == 2) ? 1.0f : 0.5f;
        sB2[tid] = s * (bih2[tid] + bhh2[tid]);
    }
    __syncthreads();

    // ---------------- warp-local tilings ----------------
    const int u01 = 2 * lane;               // layer1: lanes span 64 units
    const int u02 = 2 * (lane & 15);        // layer2: 16 lanes span 32 units
    const int bh2 = (lane >> 4) * 4;        // layer2: half-warp batch split (4 each)

    const u64t bia1_0 = lds64(&sB1[0 * H1 + u01]);
    const u64t bia1_1 = lds64(&sB1[1 * H1 + u01]);
    const u64t bia1_2 = lds64(&sB1[2 * H1 + u01]);
    const u64t bia1_3 = lds64(&sB1[3 * H1 + u01]);
    const u64t bia2_0 = lds64(&sB2[0 * H2 + u02]);
    const u64t bia2_1 = lds64(&sB2[1 * H2 + u02]);
    const u64t bia2_2 = lds64(&sB2[2 * H2 + u02]);
    const u64t bia2_3 = lds64(&sB2[3 * H2 + u02]);

    const int gw = wid * GRID + blockIdx.x;

    for (int tau = gw; tau < NTASKS; tau += WSLOTS) {
        const float* xg = x + (size_t)tau * TB * (TT * DD);

        for (int i = lane; i < H1 * HS1; i += 32) sH1w[i] = 0.0f;
        for (int i = lane; i < H2 * HS2; i += 32) sH2w[i] = 0.0f;
        __syncwarp();

        // c1[u][b]: u = unit half (u01+u), b = batch 0..7
        float c1[2][TB];
        #pragma unroll
        for (int u = 0; u < 2; u++)
            #pragma unroll
            for (int b = 0; b < TB; b++) c1[u][b] = 0.0f;
        float c2[2][4];
        #pragma unroll
        for (int u = 0; u < 2; u++)
            #pragma unroll
            for (int b = 0; b < 4; b++) c2[u][b] = 0.0f;

        float xr[2];
        #pragma unroll
        for (int j = 0; j < 2; j++) {
            int idx = 32 * j + lane;
            if (idx < DD * TB) {
                int b = idx / DD, d = idx - b * DD;
                xr[j] = xg[b * (TT * DD) + d];
            }
        }

        for (int t = 0; t < TT; t++) {
            #pragma unroll
            for (int j = 0; j < 2; j++) {
                int idx = 32 * j + lane;
                if (idx < DD * TB) {
                    int b = idx / DD, d = idx - b * DD;
                    sXw[d * XS + b] = xr[j];
                }
            }
            __syncwarp();
            if (t + 1 < TT) {
                #pragma unroll
                for (int j = 0; j < 2; j++) {
                    int idx = 32 * j + lane;
                    if (idx < DD * TB) {
                        int b = idx / DD, d = idx - b * DD;
                        xr[j] = xg[b * (TT * DD) + (t + 1) * DD + d];
                    }
                }
            }

            // ================= layer 1 gates (diagonal f32x2) =================
            // aA[g][p] = (gate[u0][b0], gate[u1][b1]); aB[g][p] = (gate[u0][b1], gate[u1][b0])
            u64t aA[4][4], aB[4][4];
            #pragma unroll
            for (int p = 0; p < 4; p++) {
                aA[0][p] = bia1_0; aB[0][p] = bia1_0;
                aA[1][p] = bia1_1; aB[1][p] = bia1_1;
                aA[2][p] = bia1_2; aB[2][p] = bia1_2;
                aA[3][p] = bia1_3; aB[3][p] = bia1_3;
            }
            #pragma unroll
            for (int d = 0; d < DD; d++) {
                u64t wv0 = lds64(&sW1T[d * G1 + 0 * H1 + u01]);
                u64t wv1 = lds64(&sW1T[d * G1 + 1 * H1 + u01]);
                u64t wv2 = lds64(&sW1T[d * G1 + 2 * H1 + u01]);
                u64t wv3 = lds64(&sW1T[d * G1 + 3 * H1 + u01]);
                #pragma unroll
                for (int p = 0; p < 4; p++) {
                    u64t xv = lds64(&sXw[d * XS + 2 * p]);
                    u64t xs = swp(xv);
                    aA[0][p] = fma2(wv0, xv, aA[0][p]); aB[0][p] = fma2(wv0, xs, aB[0][p]);
                    aA[1][p] = fma2(wv1, xv, aA[1][p]); aB[1][p] = fma2(wv1, xs, aB[1][p]);
                    aA[2][p] = fma2(wv2, xv, aA[2][p]); aB[2][p] = fma2(wv2, xs, aB[2][p]);
                    aA[3][p] = fma2(wv3, xv, aA[3][p]); aB[3][p] = fma2(wv3, xs, aB[3][p]);
                }
            }
            #pragma unroll 2
            for (int k = 0; k < H1; k++) {
                u64t wv0 = lds64(&sW1T[(DD + k) * G1 + 0 * H1 + u01]);
                u64t wv1 = lds64(&sW1T[(DD + k) * G1 + 1 * H1 + u01]);
                u64t wv2 = lds64(&sW1T[(DD + k) * G1 + 2 * H1 + u01]);
                u64t wv3 = lds64(&sW1T[(DD + k) * G1 + 3 * H1 + u01]);
                #pragma unroll
                for (int p = 0; p < 4; p++) {
                    u64t hv = lds64(&sH1w[k * HS1 + 2 * p]);
                    u64t hs = swp(hv);
                    aA[0][p] = fma2(wv0, hv, aA[0][p]); aB[0][p] = fma2(wv0, hs, aB[0][p]);
                    aA[1][p] = fma2(wv1, hv, aA[1][p]); aB[1][p] = fma2(wv1, hs, aB[1][p]);
                    aA[2][p] = fma2(wv2, hv, aA[2][p]); aB[2][p] = fma2(wv2, hs, aB[2][p]);
                    aA[3][p] = fma2(wv3, hv, aA[3][p]); aB[3][p] = fma2(wv3, hs, aB[3][p]);
                }
            }
            __syncwarp();                      // WAR on old h1

            // pointwise layer1: unpack diagonals, write new h1
            #pragma unroll
            for (int p = 0; p < 4; p++) {
                float iA0, iA1, fA0, fA1, gA0, gA1, oA0, oA1;
                float iB0, iB1, fB0, fB1, gB0, gB1, oB0, oB1;
                upk(aA[0][p], iA0, iA1); upk(aB[0][p], iB0, iB1);
                upk(aA[1][p], fA0, fA1); upk(aB[1][p], fB0, fB1);
                upk(aA[2][p], gA0, gA1); upk(aB[2][p], gB0, gB1);
                upk(aA[3][p], oA0, oA1); upk(aB[3][p], oB0, oB1);
                // e(u,b): A.lo=(u0,b0) A.hi=(u1,b1) B.lo=(u0,b1) B.hi=(u1,b0)
                float c00 = sig_h(fA0) * c1[0][2*p]   + sig_h(iA0) * tanha(gA0);
                float c11 = sig_h(fA1) * c1[1][2*p+1] + sig_h(iA1) * tanha(gA1);
                float c01 = sig_h(fB0) * c1[0][2*p+1] + sig_h(iB0) * tanha(gB0);
                float c10 = sig_h(fB1) * c1[1][2*p]   + sig_h(iB1) * tanha(gB1);
                c1[0][2*p]   = c00; c1[1][2*p+1] = c11;
                c1[0][2*p+1] = c01; c1[1][2*p]   = c10;
                float h00 = sig_h(oA0) * tanha(c00);
                float h11 = sig_h(oA1) * tanha(c11);
                float h01 = sig_h(oB0) * tanha(c01);
                float h10 = sig_h(oB1) * tanha(c10);
                sts64(&sH1w[(u01 + 0) * HS1 + 2 * p], pk2(h00, h01));
                sts64(&sH1w[(u01 + 1) * HS1 + 2 * p], pk2(h10, h11));
            }
            __syncwarp();                      // RAW: new h1 visible

            // ================= layer 2 gates (diagonal f32x2) =================
            u64t bA[4][2], bB[4][2];
            #pragma unroll
            for (int p = 0; p < 2; p++) {
                bA[0][p] = bia2_0; bB[0][p] = bia2_0;
                bA[1][p] = bia2_1; bB[1][p] = bia2_1;
                bA[2][p] = bia2_2; bB[2][p] = bia2_2;
                bA[3][p] = bia2_3; bB[3][p] = bia2_3;
            }
            #pragma unroll 2
            for (int k = 0; k < H1; k++) {     // input = new h1
                u64t wv0 = lds64(&sW2T[k * G2 + 0 * H2 + u02]);
                u64t wv1 = lds64(&sW2T[k * G2 + 1 * H2 + u02]);
                u64t wv2 = lds64(&sW2T[k * G2 + 2 * H2 + u02]);
                u64t wv3 = lds64(&sW2T[k * G2 + 3 * H2 + u02]);
                #pragma unroll
                for (int p = 0; p < 2; p++) {
                    u64t hv = lds64(&sH1w[k * HS1 + bh2 + 2 * p]);
                    u64t hs = swp(hv);
                    bA[0][p] = fma2(wv0, hv, bA[0][p]); bB[0][p] = fma2(wv0, hs, bB[0][p]);
                    bA[1][p] = fma2(wv1, hv, bA[1][p]); bB[1][p] = fma2(wv1, hs, bB[1][p]);
                    bA[2][p] = fma2(wv2, hv, bA[2][p]); bB[2][p] = fma2(wv2, hs, bB[2][p]);
                    bA[3][p] = fma2(wv3, hv, bA[3][p]); bB[3][p] = fma2(wv3, hs, bB[3][p]);
                }
            }
            #pragma unroll 2
            for (int k = 0; k < H2; k++) {     // recurrent = old h2
                u64t wv0 = lds64(&sW2T[(H1 + k) * G2 + 0 * H2 + u02]);
                u64t wv1 = lds64(&sW2T[(H1 + k) * G2 + 1 * H2 + u02]);
                u64t wv2 = lds64(&sW2T[(H1 + k) * G2 + 2 * H2 + u02]);
                u64t wv3 = lds64(&sW2T[(H1 + k) * G2 + 3 * H2 + u02]);
                #pragma unroll
                for (int p = 0; p < 2; p++) {
                    u64t hv = lds64(&sH2w[k * HS2 + bh2 + 2 * p]);
                    u64t hs = swp(hv);
                    bA[0][p] = fma2(wv0, hv, bA[0][p]); bB[0][p] = fma2(wv0, hs, bB[0][p]);
                    bA[1][p] = fma2(wv1, hv, bA[1][p]); bB[1][p] = fma2(wv1, hs, bB[1][p]);
                    bA[2][p] = fma2(wv2, hv, bA[2][p]); bB[2][p] = fma2(wv2, hs, bB[2][p]);
                    bA[3][p] = fma2(wv3, hv, bA[3][p]); bB[3][p] = fma2(wv3, hs, bB[3][p]);
                }
            }
            __syncwarp();                      // WAR on old h2

            // pointwise layer2
            #pragma unroll
            for (int p = 0; p < 2; p++) {
                float iA0, iA1, fA0, fA1, gA0, gA1, oA0, oA1;
                float iB0, iB1, fB0, fB1, gB0, gB1, oB0, oB1;
                upk(bA[0][p], iA0, iA1); upk(bB[0][p], iB0, iB1);
                upk(bA[1][p], fA0, fA1); upk(bB[1][p], fB0, fB1);
                upk(bA[2][p], gA0, gA1); upk(bB[2][p], gB0, gB1);
                upk(bA[3][p], oA0, oA1); upk(bB[3][p], oB0, oB1);
                float c00 = sig_h(fA0) * c2[0][2*p]   + sig_h(iA0) * tanha(gA0);
                float c11 = sig_h(fA1) * c2[1][2*p+1] + sig_h(iA1) * tanha(gA1);
                float c01 = sig_h(fB0) * c2[0][2*p+1] + sig_h(iB0) * tanha(gB0);
                float c10 = sig_h(fB1) * c2[1][2*p]   + sig_h(iB1) * tanha(gB1);
                c2[0][2*p]   = c00; c2[1][2*p+1] = c11;
                c2[0][2*p+1] = c01; c2[1][2*p]   = c10;
                float h00 = sig_h(oA0) * tanha(c00);
                float h11 = sig_h(oA1) * tanha(c11);
                float h01 = sig_h(oB0) * tanha(c01);
                float h10 = sig_h(oB1) * tanha(c10);
                sts64(&sH2w[(u02 + 0) * HS2 + bh2 + 2 * p], pk2(h00, h01));
                sts64(&sH2w[(u02 + 1) * HS2 + bh2 + 2 * p], pk2(h10, h11));
            }
            __syncwarp();                      // new h2 visible
        }

        // ================= head: dense(16)+relu -> dot(16)+sigmoid =============
        if (lane < TB) {
            const int b = lane;
            float hv[H2];
            #pragma unroll
            for (int k = 0; k < H2; k++) hv[k] = sH2w[k * HS2 + b];
            float o = __ldg(&bo[0]);
            #pragma unroll
            for (int j = 0; j < 16; j++) {
                float s = __ldg(&bd[j]);
                #pragma unroll
                for (int k = 0; k < H2; k++) s += hv[k] * __ldg(&Wd[j * H2 + k]);
                o += fmaxf(s, 0.0f) * __ldg(&Wo[j]);
            }
            out[tau * TB + b] = sigx(o);
        }
        __syncwarp();
    }
}

extern "C" void kernel_launch(void* const* d_in, const int* in_sizes, int n_in,
                              void* d_out, int out_size) {
    const float* x    = (const float*)d_in[0];
    const float* Wih1 = (const float*)d_in[1];
    const float* Whh1 = (const float*)d_in[2];
    const float* bih1 = (const float*)d_in[3];
    const float* bhh1 = (const float*)d_in[4];
    const float* Wih2 = (const float*)d_in[5];
    const float* Whh2 = (const float*)d_in[6];
    const float* bih2 = (const float*)d_in[7];
    const float* bhh2 = (const float*)d_in[8];
    const float* Wd   = (const float*)d_in[9];
    const float* bd   = (const float*)d_in[10];
    const float* Wo   = (const float*)d_in[11];
    const float* bo   = (const float*)d_in[12];
    float* out = (float*)d_out;

    static bool attr_set = false;
    if (!attr_set) {
        cudaFuncSetAttribute(momentum_lstm_kernel,
                             cudaFuncAttributeMaxDynamicSharedMemorySize, SMEM_BYTES);
        attr_set = true;
    }

    momentum_lstm_kernel<<<GRID, NT, SMEM_BYTES>>>(
        x, Wih1, Whh1, bih1, bhh1, Wih2, Whh2, bih2, bhh2, Wd, bd, Wo, bo, out);
}